// round 16
// baseline (speedup 1.0000x reference)
#include <cuda_runtime.h>

#define NN  400
#define FF  240
#define CC  32
#define LL  1440

// ---------------- scratch (device globals; no allocation allowed) ----------------
__device__ __align__(16) float g_U[NN*CC];
__device__ __align__(16) float g_V[NN*CC];
__device__ __align__(16) float g_aggi[NN*CC];
__device__ __align__(16) float g_aggj[NN*CC];
__device__ __align__(16) float g_e2 [NN*NN];
__device__ __align__(16) float g_e2T[NN*NN];
__device__ __align__(16) float g_aT [NN*NN];
__device__ __align__(16) float g_eT [NN*NN];
__device__ __align__(16) float g_x2[NN*FF];
__device__ __align__(16) float g_x3[NN*FF];
__device__ __align__(16) float g_W2[304*64];   // nw1 @ [sw2U | sw2V]
__device__ __align__(16) float g_b2[64];       // nb1 @ [sw2U | sw2V]

// ---------------- uv v3 body: [U|V](2 rows) with 8-way K-split ----------------
__device__ __forceinline__ void uv3_body(
    const float* __restrict__ x, const float* __restrict__ sw,
    float* __restrict__ U, float* __restrict__ V,
    int r0, int tid, float* xs /*2*FF*/, float* red /*7*2*64*/)
{
    for (int idx = tid; idx < 2 * FF / 4; idx += 512)
        ((float4*)xs)[idx] = ((const float4*)(x + r0 * FF))[idx];
    __syncthreads();

    int kq   = tid >> 6;          // 0..7
    int slot = tid & 63;
    int half = slot >> 5;         // 0 -> U, 1 -> V
    int c    = slot & 31;
    int kbeg = kq * 30;

    const float* wp = sw + (half * FF + kbeg) * CC + c;
    float w0 = __ldg(wp);
    float w1 = __ldg(wp + CC);
    float a0 = 0.f, a1 = 0.f;
    const float* x0 = xs + kbeg;
    const float* x1 = xs + FF + kbeg;
#pragma unroll
    for (int k = 0; k < 30; k += 2) {
        float n0 = w0, n1 = w1;
        if (k + 2 < 30) {
            n0 = __ldg(wp + 2 * CC);
            n1 = __ldg(wp + 3 * CC);
        }
        a0 = fmaf(x0[k],     w0, a0);
        a1 = fmaf(x1[k],     w0, a1);
        a0 = fmaf(x0[k + 1], w1, a0);
        a1 = fmaf(x1[k + 1], w1, a1);
        w0 = n0; w1 = n1;
        wp += 2 * CC;
    }
    if (kq > 0) {
        red[(kq - 1) * 128 + slot]      = a0;
        red[(kq - 1) * 128 + 64 + slot] = a1;
    }
    __syncthreads();
    if (kq == 0) {
        float s0 = a0, s1 = a1;
#pragma unroll
        for (int q = 0; q < 7; q++) {
            s0 += red[q * 128 + slot];
            s1 += red[q * 128 + 64 + slot];
        }
        float* dst = half ? V : U;
        dst[r0 * CC + c]       = s0;
        dst[(r0 + 1) * CC + c] = s1;
    }
}

// ---------------- fused prologue ----------------
// y=0: a->aT (x<169)   y=1: e->eT (x<169)   y=2: uv3 layer1 (x<200)
// y=3: W2/b2 compose (x<305; one W2 row per block, x==304 -> b2)
__global__ __launch_bounds__(512) void pre_kernel(
    const float* __restrict__ a, float* __restrict__ aT,
    const float* __restrict__ e, float* __restrict__ eT,
    const float* __restrict__ x, const float* __restrict__ sw,
    float* __restrict__ U, float* __restrict__ V,
    const float* __restrict__ nw1, const float* __restrict__ nb1,
    const float* __restrict__ sw2,
    float* __restrict__ W2, float* __restrict__ b2)
{
    __shared__ float smem[2 * FF + 7 * 2 * 64 + 64];
    int tid = threadIdx.x;
    if (blockIdx.y < 2) {
        if (blockIdx.x >= 169) return;
        const float* src = blockIdx.y ? e : a;
        float*       dst = blockIdx.y ? eT : aT;
        float (*tile)[33] = (float(*)[33])smem;
        int tx = tid & 31, ty = tid >> 5;   // ty 0..15
        int bx = blockIdx.x % 13, by = blockIdx.x / 13;
        int xc = bx * 32 + tx;
#pragma unroll
        for (int dy = 0; dy < 32; dy += 16) {
            int yr = by * 32 + ty + dy;
            if (xc < NN && yr < NN)
                tile[ty + dy][tx] = src[yr * NN + xc];
        }
        __syncthreads();
        int xc2 = by * 32 + tx;
#pragma unroll
        for (int dy = 0; dy < 32; dy += 16) {
            int yr2 = bx * 32 + ty + dy;
            if (xc2 < NN && yr2 < NN)
                dst[yr2 * NN + xc2] = tile[tx][ty + dy];
        }
    } else if (blockIdx.y == 2) {
        if (blockIdx.x >= 200) return;
        uv3_body(x, sw, U, V, blockIdx.x * 2, tid, smem, smem + 2 * FF);
    } else {
        // ---- compose: one output row per block ----
        const int KTOT = FF + 2 * CC;            // 304
        int k = blockIdx.x;
        if (k > KTOT) return;
        const float* wr = (k == KTOT) ? nb1 : (nw1 + k * FF);
        float* dst = (k == KTOT) ? b2 : (W2 + k * 64);

        // stage the 240-float source row
        if (tid < FF) smem[tid] = __ldg(&wr[tid]);
        __syncthreads();

        int fq = tid >> 6;            // 0..7
        int c  = tid & 63;
        int fbeg = fq * 30;
        // sw2 column c: U cols 0-31 at sw2[f*32+c]; V cols 32-63 at sw2[240*32 + f*32 + c-32]
        const float* sc = (c < CC) ? (sw2 + c) : (sw2 + FF * CC + (c - CC));
        const float* sp = sc + fbeg * CC;
        float w0 = __ldg(sp);
        float w1 = __ldg(sp + CC);
        float acc = 0.f;
#pragma unroll
        for (int f = 0; f < 30; f += 2) {
            float n0 = w0, n1 = w1;
            if (f + 2 < 30) {
                n0 = __ldg(sp + 2 * CC);
                n1 = __ldg(sp + 3 * CC);
            }
            acc = fmaf(smem[fbeg + f],     w0, acc);
            acc = fmaf(smem[fbeg + f + 1], w1, acc);
            w0 = n0; w1 = n1;
            sp += 2 * CC;
        }
        float* red = smem + 2 * FF;
        if (fq > 0) red[(fq - 1) * 64 + c] = acc;
        __syncthreads();
        if (fq == 0) {
            float s = acc;
#pragma unroll
            for (int q = 0; q < 7; q++) s += red[q * 64 + c];
            dst[c] = s;
        }
    }
}

// ---------------- pair v5: channel-split, register accumulators; grid (400, 2) -----
__global__ __launch_bounds__(128) void pair_both_kernel(
    const float*  __restrict__ U,
    const float*  __restrict__ V,
    const float*  __restrict__ e,
    const float*  __restrict__ eT,
    const float*  __restrict__ a,
    const float*  __restrict__ aT,
    const float*  __restrict__ we,
    const float*  __restrict__ wet,
    const float*  __restrict__ sb,
    const float*  __restrict__ aiw, const float* __restrict__ aib,
    const float*  __restrict__ ajw, const float* __restrict__ ajb,
    const float*  __restrict__ ew,  const float* __restrict__ eb,
    float* __restrict__ aggi, float* __restrict__ aggj,
    float* __restrict__ e_out, float* __restrict__ e_outT)
{
    __shared__ float4 cw4s[CC];
    __shared__ float  cews[CC];
    __shared__ float  red[128 * 9];

    int b    = blockIdx.x;
    int side = blockIdx.y;
    int tid  = threadIdx.x;

    const float*  own  = side ? V : U;
    const float4* oth4 = (const float4*)(side ? U : V);
    const float*  eFrow = (side ? eT : e)  + b * NN;
    const float*  eRrow = (side ? e  : eT) + b * NN;
    const float*  arow  = (side ? aT : a)  + b * NN;
    const float*  gw = side ? ajw : aiw;
    const float*  gb = side ? ajb : aib;
    float* agg_out = side ? aggj : aggi;
    const bool write_e = (side == 0) && (e_out != nullptr);

    if (tid < CC) {
        int c = tid;
        cw4s[c] = make_float4(own[b * CC + c] + sb[c], we[c], wet[c], gw[c]);
        cews[c] = write_e ? ew[c] : 0.f;
    }
    __syncthreads();

    int lane  = tid & 31;
    int warp  = tid >> 5;
    int cg    = lane & 3;
    int tslot = lane >> 2;
    int t0    = warp * 8 + tslot;

    float4 cw[8];
    float  ce[8];
#pragma unroll
    for (int u = 0; u < 8; u++) {
        cw[u] = cw4s[cg * 8 + u];
        ce[u] = cews[cg * 8 + u];
    }
    float gbias = gb[0];
    float ebias = write_e ? eb[0] : 0.f;

    float agg[8];
#pragma unroll
    for (int u = 0; u < 8; u++) agg[u] = 0.f;

    for (int t = t0; t < NN; t += 32) {
        float4 o0 = __ldg(&oth4[t * 8 + cg * 2]);
        float4 o1 = __ldg(&oth4[t * 8 + cg * 2 + 1]);
        float ef = __ldg(&eFrow[t]);
        float er = __ldg(&eRrow[t]);
        float am = __ldg(&arow[t]);

        float ov[8] = {o0.x, o0.y, o0.z, o0.w, o1.x, o1.y, o1.z, o1.w};
        float s[8];
        float ai = 0.f, eo = 0.f;
#pragma unroll
        for (int u = 0; u < 8; u++) {
            float pre = cw[u].x + ov[u];
            pre = fmaf(ef, cw[u].y, pre);
            pre = fmaf(er, cw[u].z, pre);
            float sv = fmaxf(pre, 0.f) * am;
            s[u] = sv;
            ai = fmaf(sv, cw[u].w, ai);
            eo = fmaf(sv, ce[u], eo);
        }
        ai += __shfl_xor_sync(0xffffffffu, ai, 1);
        ai += __shfl_xor_sync(0xffffffffu, ai, 2);
        float att = 1.f / (1.f + __expf(-(ai + gbias)));
        if (write_e) {
            eo += __shfl_xor_sync(0xffffffffu, eo, 1);
            eo += __shfl_xor_sync(0xffffffffu, eo, 2);
            if (cg == 0) {
                float ev = eo + ebias;
                e_out[b * NN + t] = ev;
                e_outT[t * NN + b] = ev;
            }
        }
#pragma unroll
        for (int u = 0; u < 8; u++)
            agg[u] = fmaf(att, s[u], agg[u]);
    }

#pragma unroll
    for (int u = 0; u < 8; u++) red[tid * 9 + u] = agg[u];
    __syncthreads();
    if (tid < CC) {
        int c   = tid;
        int cgc = c >> 3;
        int ch  = c & 7;
        float sum = 0.f;
#pragma unroll
        for (int w = 0; w < 4; w++) {
#pragma unroll
            for (int ts = 0; ts < 8; ts++)
                sum += red[(w * 32 + ts * 4 + cgc) * 9 + ch];
        }
        agg_out[b * CC + c] = sum;
    }
}

// ---------------- node v8: float2 col-pairs, 16-way K-split; optional uv2 tile -----
// grid (100, 4 [+1]): y<4 -> x2 cols (60 each); y==4 -> U2/V2 (64 cols via W2)
__global__ __launch_bounds__(512) void node_gemm_kernel(
    const float* __restrict__ x,
    const float* __restrict__ aggi,
    const float* __restrict__ aggj,
    const float* __restrict__ nw,
    const float* __restrict__ nb,
    float* __restrict__ out,
    const float* __restrict__ W2, const float* __restrict__ b2,
    float* __restrict__ U, float* __restrict__ V)
{
    const int K = FF + 2 * CC;                  // 304 = 16 * 19
    __shared__ __align__(16) float cs[304 * 4]; // transposed: cs[k*4 + r]
    __shared__ float red[15 * 256];             // kq=1..15 partials

    int r0 = blockIdx.x * 4;
    for (int idx = threadIdx.x; idx < K * 4; idx += 512) {
        int k = idx >> 2, r = idx & 3;
        int row = r0 + r;
        float v;
        if (k < FF)            v = x[row * FF + k];
        else if (k < FF + CC)  v = aggi[row * CC + (k - FF)];
        else                   v = aggj[row * CC + (k - FF - CC)];
        cs[idx] = v;
    }
    __syncthreads();

    bool uv2 = (blockIdx.y == 4);
    int kq   = threadIdx.x >> 5;          // 0..15
    int slot = threadIdx.x & 31;
    int kbeg = kq * 19;
    const float4* cs4 = (const float4*)cs;

    int wstride, col;
    const float* wbase;
    if (uv2) { wstride = 64; col = 2 * slot; wbase = W2; }
    else     { wstride = FF; col = 2 * ((slot < 30) ? slot : 29); wbase = nw + blockIdx.y * 60; }
    bool active = uv2 || (slot < 30);

    float a0 = 0.f, a1 = 0.f, a2 = 0.f, a3 = 0.f;
    float b0 = 0.f, b1 = 0.f, b2r = 0.f, b3 = 0.f;

    const float* wp = wbase + kbeg * wstride + col;
    float2 w = *(const float2*)wp;
#pragma unroll
    for (int kk = 0; kk < 19; kk++) {
        float2 nx = w;
        if (kk + 1 < 19) nx = *(const float2*)(wp + wstride);
        float4 v = cs4[kbeg + kk];
        a0 = fmaf(v.x, w.x, a0); b0  = fmaf(v.x, w.y, b0);
        a1 = fmaf(v.y, w.x, a1); b1  = fmaf(v.y, w.y, b1);
        a2 = fmaf(v.z, w.x, a2); b2r = fmaf(v.z, w.y, b2r);
        a3 = fmaf(v.w, w.x, a3); b3  = fmaf(v.w, w.y, b3);
        w = nx;
        wp += wstride;
    }

    if (active && kq > 0) {
        float* myp = red + (kq - 1) * 256 + 2 * slot;
        myp[0]   = a0; myp[1]   = b0;
        myp[64]  = a1; myp[65]  = b1;
        myp[128] = a2; myp[129] = b2r;
        myp[192] = a3; myp[193] = b3;
    }
    __syncthreads();
    if (active && kq == 0) {
        float sa[4] = {a0, a1, a2, a3};
        float sb2[4] = {b0, b1, b2r, b3};
        const float* p = red + 2 * slot;
#pragma unroll
        for (int q = 0; q < 15; q++) {
#pragma unroll
            for (int r = 0; r < 4; r++) {
                sa[r]  += p[q * 256 + r * 64];
                sb2[r] += p[q * 256 + r * 64 + 1];
            }
        }
        if (uv2) {
            float bias0 = b2[col], bias1 = b2[col + 1];
            float* dst = (col < CC) ? U : V;
            int cc = (col < CC) ? col : col - CC;
#pragma unroll
            for (int r = 0; r < 4; r++)
                *(float2*)&dst[(r0 + r) * CC + cc] =
                    make_float2(sa[r] + bias0, sb2[r] + bias1);
        } else {
            int ocol = blockIdx.y * 60 + col;
            float bias0 = nb[ocol], bias1 = nb[ocol + 1];
#pragma unroll
            for (int r = 0; r < 4; r++)
                *(float2*)&out[(r0 + r) * FF + ocol] =
                    make_float2(sa[r] + bias0, sb2[r] + bias1);
        }
    }
}

// ---------------- final dense v4: 5-way K-split, window-4 prefetch ----------------
__global__ __launch_bounds__(480) void dense_kernel(
    const float* __restrict__ x,
    const float* __restrict__ dw,
    const float* __restrict__ db,
    float* __restrict__ out)
{
    const int KQ = 48;
    __shared__ __align__(16) float xs[FF * 16];
    __shared__ float red[4 * 16 * 96];

    int r0 = blockIdx.x * 16;
    int c0 = blockIdx.y * 96;
    for (int idx = threadIdx.x; idx < FF * 16; idx += 480) {
        int k = idx >> 4, r = idx & 15;
        xs[idx] = x[(r0 + r) * FF + k];
    }
    __syncthreads();

    int kq = threadIdx.x / 96;
    int c  = threadIdx.x % 96;
    int col = c0 + c;
    int kbeg = kq * KQ;

    float acc[16];
#pragma unroll
    for (int r = 0; r < 16; r++) acc[r] = 0.f;

    const float4* xs4 = (const float4*)xs;
    const float* wp = dw + kbeg * LL + col;
    float w0 = __ldg(wp);
    float w1 = __ldg(wp + LL);
    float w2 = __ldg(wp + 2 * LL);
    float w3 = __ldg(wp + 3 * LL);
    for (int k2 = kbeg; k2 < kbeg + KQ; k2 += 4) {
        float n0 = w0, n1 = w1, n2 = w2, n3 = w3;
        if (k2 + 4 < kbeg + KQ) {
            const float* np = wp + 4 * LL;
            n0 = __ldg(np);
            n1 = __ldg(np + LL);
            n2 = __ldg(np + 2 * LL);
            n3 = __ldg(np + 3 * LL);
        }
#pragma unroll
        for (int kk = 0; kk < 4; kk++) {
            float wf = (kk == 0) ? w0 : (kk == 1) ? w1 : (kk == 2) ? w2 : w3;
            float4 a0 = xs4[(k2 + kk) * 4 + 0];
            float4 a1 = xs4[(k2 + kk) * 4 + 1];
            float4 a2 = xs4[(k2 + kk) * 4 + 2];
            float4 a3 = xs4[(k2 + kk) * 4 + 3];
            acc[ 0] = fmaf(a0.x, wf, acc[ 0]);
            acc[ 1] = fmaf(a0.y, wf, acc[ 1]);
            acc[ 2] = fmaf(a0.z, wf, acc[ 2]);
            acc[ 3] = fmaf(a0.w, wf, acc[ 3]);
            acc[ 4] = fmaf(a1.x, wf, acc[ 4]);
            acc[ 5] = fmaf(a1.y, wf, acc[ 5]);
            acc[ 6] = fmaf(a1.z, wf, acc[ 6]);
            acc[ 7] = fmaf(a1.w, wf, acc[ 7]);
            acc[ 8] = fmaf(a2.x, wf, acc[ 8]);
            acc[ 9] = fmaf(a2.y, wf, acc[ 9]);
            acc[10] = fmaf(a2.z, wf, acc[10]);
            acc[11] = fmaf(a2.w, wf, acc[11]);
            acc[12] = fmaf(a3.x, wf, acc[12]);
            acc[13] = fmaf(a3.y, wf, acc[13]);
            acc[14] = fmaf(a3.z, wf, acc[14]);
            acc[15] = fmaf(a3.w, wf, acc[15]);
        }
        w0 = n0; w1 = n1; w2 = n2; w3 = n3;
        wp += 4 * LL;
    }

    if (kq > 0) {
        float* myp = red + (kq - 1) * 1536 + c;
#pragma unroll
        for (int r = 0; r < 16; r++) myp[r * 96] = acc[r];
    }
    __syncthreads();
    if (kq == 0) {
        float bias = db[col];
        const float* p = red + c;
#pragma unroll
        for (int r = 0; r < 16; r++)
            out[(r0 + r) * LL + col] = acc[r] + bias + p[r * 96] + p[1536 + r * 96]
                                       + p[3072 + r * 96] + p[4608 + r * 96];
    }
}

// ---------------- launch ----------------
extern "C" void kernel_launch(void* const* d_in, const int* in_sizes, int n_in,
                              void* d_out, int out_size)
{
    const float* x      = (const float*)d_in[0];
    const float* a      = (const float*)d_in[1];
    const float* e      = (const float*)d_in[2];
    const float* c1_sw  = (const float*)d_in[3];
    const float* c1_sb  = (const float*)d_in[4];
    const float* c1_aiw = (const float*)d_in[5];
    const float* c1_aib = (const float*)d_in[6];
    const float* c1_ajw = (const float*)d_in[7];
    const float* c1_ajb = (const float*)d_in[8];
    const float* c1_nw  = (const float*)d_in[9];
    const float* c1_nb  = (const float*)d_in[10];
    const float* c1_ew  = (const float*)d_in[11];
    const float* c1_eb  = (const float*)d_in[12];
    const float* c2_sw  = (const float*)d_in[13];
    const float* c2_sb  = (const float*)d_in[14];
    const float* c2_aiw = (const float*)d_in[15];
    const float* c2_aib = (const float*)d_in[16];
    const float* c2_ajw = (const float*)d_in[17];
    const float* c2_ajb = (const float*)d_in[18];
    const float* c2_nw  = (const float*)d_in[19];
    const float* c2_nb  = (const float*)d_in[20];
    const float* c2_ew  = (const float*)d_in[21];
    const float* c2_eb  = (const float*)d_in[22];
    const float* dw     = (const float*)d_in[23];
    const float* db     = (const float*)d_in[24];
    float* out = (float*)d_out;

    float *pU, *pV, *pAi, *pAj, *pE2, *pE2T, *pAT, *pET, *pX2, *pX3, *pW2, *pB2;
    cudaGetSymbolAddress((void**)&pU,   g_U);
    cudaGetSymbolAddress((void**)&pV,   g_V);
    cudaGetSymbolAddress((void**)&pAi,  g_aggi);
    cudaGetSymbolAddress((void**)&pAj,  g_aggj);
    cudaGetSymbolAddress((void**)&pE2,  g_e2);
    cudaGetSymbolAddress((void**)&pE2T, g_e2T);
    cudaGetSymbolAddress((void**)&pAT,  g_aT);
    cudaGetSymbolAddress((void**)&pET,  g_eT);
    cudaGetSymbolAddress((void**)&pX2,  g_x2);
    cudaGetSymbolAddress((void**)&pX3,  g_x3);
    cudaGetSymbolAddress((void**)&pW2,  g_W2);
    cudaGetSymbolAddress((void**)&pB2,  g_b2);

    // fused prologue: transposes + layer-1 UV + W2/b2 compose (all parallel)
    pre_kernel<<<dim3(305, 4), 512>>>(a, pAT, e, pET, x, c1_sw, pU, pV,
                                      c1_nw, c1_nb, c2_sw, pW2, pB2);

    // ---- layer 1 ----
    pair_both_kernel<<<dim3(NN, 2), 128>>>(pU, pV, e, pET, a, pAT,
        c1_sw + 480 * CC, c1_sw + 481 * CC, c1_sb,
        c1_aiw, c1_aib, c1_ajw, c1_ajb, c1_ew, c1_eb,
        pAi, pAj, pE2, pE2T);
    // node layer1: emits x2 AND U2/V2 (y==4 tile) — uv3 launch eliminated
    node_gemm_kernel<<<dim3(100, 5), 512>>>(x, pAi, pAj, c1_nw, c1_nb, pX2,
                                            pW2, pB2, pU, pV);

    // ---- layer 2 ----
    pair_both_kernel<<<dim3(NN, 2), 128>>>(pU, pV, pE2, pE2T, a, pAT,
        c2_sw + 480 * CC, c2_sw + 481 * CC, c2_sb,
        c2_aiw, c2_aib, c2_ajw, c2_ajb, nullptr, nullptr,
        pAi, pAj, nullptr, nullptr);
    node_gemm_kernel<<<dim3(100, 4), 512>>>(pX2, pAi, pAj, c2_nw, c2_nb, pX3,
                                            pW2, pB2, nullptr, nullptr);

    // ---- final dense ----
    dense_kernel<<<dim3(25, 15), 480>>>(pX3, dw, db, out);
}